// round 17
// baseline (speedup 1.0000x reference)
#include <cuda_runtime.h>
#include <cuda_bf16.h>
#include <mma.h>

#define N 512
#define D 128
#define A 4
#define T 1024
#define GRID (N / A)      // 128
#define RS 520
#define NPOS_MAX 64
#define MARGIN 1.0f
#define EPSF 1e-8f

#define EB_LD 136                       // bf16 ldm for E tile (17 x 16B: conflict-free)
#define B_LD  24                        // bf16 ldm for B tile (3 x 16B mod 8: conflict-free)
#define SZ_EB (N * EB_LD * 2)           // 139264
#define SZ_B  (D * B_LD * 2)            // 6144
#define SZ_D  (32 * 256 * 4)            // 32768
#define DYN_TOTAL (SZ_EB + SZ_B + SZ_D) // 178176

using namespace nvcuda;

__device__ double       g_psum[GRID];
__device__ unsigned int g_pcnt[GRID];
__device__ unsigned int g_done;

__global__ __launch_bounds__(T, 1) void triplet_k(const float* __restrict__ E,
                                                  const int* __restrict__ lab,
                                                  float* __restrict__ out) {
    extern __shared__ char dyn[];
    __nv_bfloat16* s_eb = (__nv_bfloat16*)dyn;                    // [512][136]
    __nv_bfloat16* s_b  = (__nv_bfloat16*)(dyn + SZ_EB);          // [128][24]
    float*         s_d  = (float*)(dyn + SZ_EB + SZ_B);           // [32][16*16]

    __shared__ float        s_row[A * RS];
    __shared__ float        s_prow[A * NPOS_MAX];
    __shared__ int          s_lab[N];
    __shared__ short        s_pos[A][NPOS_MAX];
    __shared__ int          s_np[A];
    __shared__ double       s_wsum[T / 32];
    __shared__ unsigned int s_wcnt[T / 32];
    __shared__ int          s_last;

    const int i0   = blockIdx.x * A;
    const int tid  = threadIdx.x;
    const int lane = tid & 31;
    const int w    = tid >> 5;            // 32 warps

    if (tid < A) s_np[tid] = 0;
    if (tid < N) s_lab[tid] = lab[tid];
    __syncthreads();

    // positives (threads 0..511)
    if (tid < N) {
        const int lj = s_lab[tid];
#pragma unroll
        for (int a = 0; a < A; a++) {
            if (tid != i0 + a && lj == s_lab[i0 + a]) {
                int p = atomicAdd(&s_np[a], 1);
                s_pos[a][p] = (short)tid;
            }
        }
    }

    // ---- stage: convert E (f32) -> s_eb (bf16, ldm 136), coalesced float2 reads ----
    for (int idx = tid; idx < N * D / 2; idx += T) {
        const int row = idx >> 6;         // D/2 == 64 pairs per row
        const int p   = idx & 63;
        const float2 v = *(const float2*)(E + row * D + 2 * p);
        *(__nv_bfloat162*)(s_eb + row * EB_LD + 2 * p) = __float22bfloat162_rn(v);
    }
    // ---- stage B: anchors k-major, 16 cols (4 real + 12 zero), ldm 24 ----
    if (tid < D) {
        const int k = tid;
#pragma unroll
        for (int a = 0; a < A; a++)
            s_b[k * B_LD + a] = __float2bfloat16(E[(i0 + a) * D + k]);
#pragma unroll
        for (int a = A; a < 16; a++)
            s_b[k * B_LD + a] = __float2bfloat16(0.0f);
    }
    __syncthreads();

    // ---- dot phase: warp w computes rows [16w,16w+16) x 16 anchors via wmma ----
    {
        wmma::fragment<wmma::matrix_a, 16, 16, 16, __nv_bfloat16, wmma::row_major> af;
        wmma::fragment<wmma::matrix_b, 16, 16, 16, __nv_bfloat16, wmma::row_major> bf;
        wmma::fragment<wmma::accumulator, 16, 16, 16, float> df;
        wmma::fill_fragment(df, 0.0f);

        const __nv_bfloat16* abase = s_eb + (w << 4) * EB_LD;
#pragma unroll
        for (int k = 0; k < 8; k++) {
            wmma::load_matrix_sync(af, abase + k * 16, EB_LD);
            wmma::load_matrix_sync(bf, s_b + (k * 16) * B_LD, B_LD);
            wmma::mma_sync(df, af, bf, df);
        }
        wmma::store_matrix_sync(s_d + w * 256, df, 16, wmma::mem_row_major);
        __syncwarp();

        // copy the 4 valid anchor columns into s_row
        for (int v = lane; v < 64; v += 32) {
            const int r  = v >> 2;
            const int aa = v & 3;
            s_row[aa * RS + (w << 4) + r] = s_d[w * 256 + r * 16 + aa];
        }
    }
    __syncthreads();

    // ---- compact positive row values ----
    if (tid < A * NPOS_MAX) {
        const int a = tid >> 6;
        const int p = tid & 63;
        if (p < s_np[a]) s_prow[(a << 6) + p] = s_row[a * RS + s_pos[a][p]];
    }
    __syncthreads();

    // ---- hinge phase: thread owns k; half-split over positives ----
    float lsum = 0.f;
    unsigned int lcnt = 0;
    {
        const int k    = tid & (N - 1);
        const int h    = tid >> 9;
        const int labk = s_lab[k];
        const float tv[A] = { MARGIN - s_row[0 * RS + k], MARGIN - s_row[1 * RS + k],
                              MARGIN - s_row[2 * RS + k], MARGIN - s_row[3 * RS + k] };

#pragma unroll
        for (int a = 0; a < A; a++) {
            if (labk != s_lab[i0 + a]) {
                const int    np = s_np[a];
                const float  ta = tv[a];
                const float* pr = s_prow + (a << 6);
                for (int p = h; p < np; p += 2) {
                    const float v = pr[p] + ta;
                    if (v > 0.f)  lsum += v;
                    if (v > EPSF) lcnt++;
                }
            }
        }
    }

    // ---- block reduction ----
    double dsum = (double)lsum;
#pragma unroll
    for (int o = 16; o > 0; o >>= 1) {
        dsum += __shfl_down_sync(0xffffffffu, dsum, o);
        lcnt += __shfl_down_sync(0xffffffffu, lcnt, o);
    }
    if (lane == 0) { s_wsum[w] = dsum; s_wcnt[w] = lcnt; }
    __syncthreads();

    // ---- epilogue: contention-free partials + single counter atomic ----
    if (tid == 0) {
        double t = 0.0;
        unsigned int c = 0;
#pragma unroll
        for (int ww = 0; ww < T / 32; ww++) { t += s_wsum[ww]; c += s_wcnt[ww]; }
        g_psum[blockIdx.x] = t;
        g_pcnt[blockIdx.x] = c;
        __threadfence();
        const unsigned int d = atomicAdd(&g_done, 1u);
        s_last = (d == GRID - 1);
    }
    __syncthreads();

    // ---- last CTA reduces the 128 partials ----
    if (s_last) {
        if (tid < GRID) {
            double t = g_psum[tid];
            unsigned int c = g_pcnt[tid];
#pragma unroll
            for (int o = 16; o > 0; o >>= 1) {
                t += __shfl_down_sync(0xffffffffu, t, o);
                c += __shfl_down_sync(0xffffffffu, c, o);
            }
            if (lane == 0) { s_wsum[w] = t; s_wcnt[w] = c; }
        }
        __syncthreads();
        if (tid == 0) {
            double t = 0.0;
            unsigned int c = 0;
#pragma unroll
            for (int ww = 0; ww < GRID / 32; ww++) { t += s_wsum[ww]; c += s_wcnt[ww]; }
            out[0] = (float)(t / ((double)c + (double)EPSF));
            atomicExch(&g_done, 0u);
        }
    }
}

extern "C" void kernel_launch(void* const* d_in, const int* in_sizes, int n_in,
                              void* d_out, int out_size) {
    const float* E   = (const float*)d_in[0];
    const int*   lab = (const int*)d_in[1];
    float*       out = (float*)d_out;

    cudaFuncSetAttribute(triplet_k, cudaFuncAttributeMaxDynamicSharedMemorySize, DYN_TOTAL);
    triplet_k<<<GRID, T, DYN_TOTAL>>>(E, lab, out);
}